// round 11
// baseline (speedup 1.0000x reference)
#include <cuda_runtime.h>
#include <cuda_bf16.h>
#include <math.h>
#include <stdint.h>

// Problem dims (fixed by reference)
#define BB 2
#define NN 2048
#define DD 1024
#define HH 16
#define DHH 64
#define HID 4096
#define D3 3072
#define ROWS (BB*NN)          // 4096

// ---------------- scratch (static device arrays; no allocation) -------------
__device__ float g_xn[ROWS * DD];
__device__ float g_qkv[ROWS * D3];
__device__ float g_x1[ROWS * DD];
__device__ float g_h[ROWS * HID];

// ======================= common helpers ======================================
__device__ __forceinline__ uint32_t smem_u32(const void* p) {
    uint32_t a;
    asm("{ .reg .u64 t; cvta.to.shared.u64 t, %1; cvt.u32.u64 %0, t; }"
        : "=r"(a) : "l"(p));
    return a;
}

__device__ __forceinline__ uint32_t f2tf32(float x) {
    uint32_t u;
    asm("cvt.rna.tf32.f32 %0, %1;" : "=r"(u) : "f"(x));
    return u;
}

// rna-equivalent rounding for HMMA-tf32 consumers: HMMA ignores the low 13
// mantissa bits, so bits+0x1000 (round half away) == cvt.rna.tf32.
#define RNA(u) ((u) + 0x1000u)

__device__ __forceinline__ void mma_tf32(float* c, const uint32_t* a, const uint32_t* b) {
    asm volatile(
        "mma.sync.aligned.m16n8k8.row.col.f32.tf32.tf32.f32 "
        "{%0,%1,%2,%3}, {%4,%5,%6,%7}, {%8,%9}, {%0,%1,%2,%3};"
        : "+f"(c[0]), "+f"(c[1]), "+f"(c[2]), "+f"(c[3])
        : "r"(a[0]), "r"(a[1]), "r"(a[2]), "r"(a[3]), "r"(b[0]), "r"(b[1]));
}

__device__ __forceinline__ void cpa4(uint32_t dst, const float* src) {
    asm volatile("cp.async.ca.shared.global [%0], [%1], 4;" :: "r"(dst), "l"(src));
}
__device__ __forceinline__ void cpa16(uint32_t dst, const float* src) {
    asm volatile("cp.async.cg.shared.global [%0], [%1], 16;" :: "r"(dst), "l"(src));
}
#define CP_COMMIT() asm volatile("cp.async.commit_group;" ::: "memory")
#define CP_WAIT2()  asm volatile("cp.async.wait_group 2;" ::: "memory")

// ======================= mma.sync tf32 GEMM ==================================
// C[M,N] = A[M,K] @ W[K,N] + bias; EPI: 0 bias, 1 gelu, 2 +res
// W consumed ROW-MAJOR directly.
// CTA tile 128x256x32, 256 threads (8 warps, 2Mx4N), warp tile 64x64
// (MF=4, NF=8 -> 1.0 LDS per MMA). 3-stage cp.async(16B) pipeline.
//   A tile [128][KPAD=40], B tile [32][NPAD=264]; pads==8 mod 32.

#define KPAD 40
#define NPAD 264
#define A_ST_F (128 * KPAD)            // 5120 floats
#define B_ST_F (32 * NPAD)             // 8448 floats
#define STAGE_F (A_ST_F + B_ST_F)      // 13568 floats
#define GEMM_SMEM_BYTES (3 * STAGE_F * 4)   // 162816 B

__device__ __forceinline__ void gemm_cp_stage(uint32_t sA, uint32_t sB,
                                              const float* __restrict__ A,
                                              const float* __restrict__ W,
                                              int K, int N, int row0, int col0,
                                              int k0, int tid) {
    // A: 128 rows x 8 chunks = 1024 chunks (l = 0..3)
    #pragma unroll
    for (int l = 0; l < 4; l++) {
        int c = tid + l * 256;
        int r = c >> 3;
        int kc = c & 7;
        cpa16(sA + (uint32_t)(r * KPAD + kc * 4) * 4,
              &A[(size_t)(row0 + r) * K + k0 + kc * 4]);
    }
    // B: 32 k-rows x 64 chunks = 2048 chunks (l = 0..7)
    #pragma unroll
    for (int l = 0; l < 8; l++) {
        int c = tid + l * 256;
        int kr = c >> 6;
        int nc = c & 63;
        cpa16(sB + (uint32_t)(kr * NPAD + nc * 4) * 4,
              &W[(size_t)(k0 + kr) * N + col0 + nc * 4]);
    }
}

template<int EPI>
__global__ __launch_bounds__(256, 1) void gemm_mma(const float* __restrict__ A,
                                                   const float* __restrict__ W,
                                                   const float* __restrict__ bias,
                                                   const float* __restrict__ res,
                                                   float* __restrict__ C,
                                                   int M, int N, int K) {
    extern __shared__ uint32_t sm[];
    uint32_t smb = smem_u32(sm);

    int tid = threadIdx.x;
    int lane = tid & 31, wid = tid >> 5;
    int warpM = wid & 1, warpN = wid >> 1;     // 2 x 4
    int gid = lane >> 2, tig = lane & 3;
    int row0 = blockIdx.y * 128, col0 = blockIdx.x * 256;

    float c[4][8][4];
    #pragma unroll
    for (int mf = 0; mf < 4; mf++)
        #pragma unroll
        for (int nf = 0; nf < 8; nf++)
            #pragma unroll
            for (int q = 0; q < 4; q++) c[mf][nf][q] = 0.0f;

    int nk = K / 32;
    gemm_cp_stage(smb, smb + A_ST_F * 4, A, W, K, N, row0, col0, 0, tid);
    CP_COMMIT();
    gemm_cp_stage(smb + STAGE_F * 4, smb + (STAGE_F + A_ST_F) * 4,
                  A, W, K, N, row0, col0, 32, tid);
    CP_COMMIT();

    for (int kt = 0; kt < nk; kt++) {
        int s = kt % 3;
        int kn = kt + 2;
        if (kn < nk) {
            int sn = kn % 3;
            gemm_cp_stage(smb + sn * STAGE_F * 4,
                          smb + (sn * STAGE_F + A_ST_F) * 4,
                          A, W, K, N, row0, col0, kn * 32, tid);
        }
        CP_COMMIT();
        CP_WAIT2();
        __syncthreads();

        const uint32_t* sA = sm + s * STAGE_F;
        const uint32_t* sB = sA + A_ST_F;
        #pragma unroll
        for (int ss = 0; ss < 4; ss++) {
            uint32_t a[4][4], b[8][2];
            #pragma unroll
            for (int mf = 0; mf < 4; mf++) {
                int base = (warpM * 64 + mf * 16 + gid) * KPAD + ss * 8 + tig;
                a[mf][0] = RNA(sA[base]);
                a[mf][1] = RNA(sA[base + 8 * KPAD]);
                a[mf][2] = RNA(sA[base + 4]);
                a[mf][3] = RNA(sA[base + 8 * KPAD + 4]);
            }
            #pragma unroll
            for (int nf = 0; nf < 8; nf++) {
                int base = (ss * 8 + tig) * NPAD + warpN * 64 + nf * 8 + gid;
                b[nf][0] = RNA(sB[base]);
                b[nf][1] = RNA(sB[base + 4 * NPAD]);
            }
            #pragma unroll
            for (int mf = 0; mf < 4; mf++)
                #pragma unroll
                for (int nf = 0; nf < 8; nf++)
                    mma_tf32(c[mf][nf], a[mf], b[nf]);
        }
        __syncthreads();
    }

    #pragma unroll
    for (int mf = 0; mf < 4; mf++) {
        #pragma unroll
        for (int nf = 0; nf < 8; nf++) {
            int col = col0 + warpN * 64 + nf * 8 + tig * 2;
            float b0 = bias[col], b1 = bias[col + 1];
            #pragma unroll
            for (int h = 0; h < 2; h++) {
                int row = row0 + warpM * 64 + mf * 16 + gid + h * 8;
                float v0 = c[mf][nf][h * 2 + 0] + b0;
                float v1 = c[mf][nf][h * 2 + 1] + b1;
                if (EPI == 1) {
                    v0 = 0.5f * v0 * (1.0f + erff(v0 * 0.70710678118654752f));
                    v1 = 0.5f * v1 * (1.0f + erff(v1 * 0.70710678118654752f));
                } else if (EPI == 2) {
                    float2 rr = *(const float2*)&res[(size_t)row * N + col];
                    v0 += rr.x; v1 += rr.y;
                }
                float2 o; o.x = v0; o.y = v1;
                *(float2*)&C[(size_t)row * N + col] = o;
            }
        }
    }
}

// ======================= mma.sync tf32 flash attention =======================
// CTA: 128 q-rows x 1 head; 8 warps x 16 rows; key tile 64; Dh=64.
// K and V^T raw fp32 in fragment-order SMEM, 3-stage cp.async pipeline;
// rna rounding applied in consumer fragment registers.
// Fused epilogue: x1 = x + attn (raw-reshape flat add).

#define ATT_BST 66
#define ATT_OP_F (64 * ATT_BST)          // 4224 floats per operand
#define ATT_STAGE_F (2 * ATT_OP_F)
#define ATT_SMEM_BYTES (3 * ATT_STAGE_F * 4)   // 101376 B

__device__ __forceinline__ void att_cp_stage(uint32_t sK, uint32_t sV,
                                             const float* __restrict__ kb,
                                             const float* __restrict__ vb,
                                             int kt0, int tid) {
    #pragma unroll
    for (int l = 0; l < 16; l++) {
        int f = tid + l * 256;           // 0..4095
        int r = f >> 6;                  // key row 0..63
        int d = f & 63;                  // dh
        uint32_t wk = (uint32_t)(((r >> 3) * 8 + (d >> 3)) * ATT_BST
                      + ((r & 7) * 4 + (d & 3)) * 2 + ((d >> 2) & 1));
        cpa4(sK + wk * 4, &kb[(size_t)(kt0 + r) * D3 + d]);
        uint32_t wv = (uint32_t)(((d >> 3) * 8 + (r >> 3)) * ATT_BST
                      + ((d & 7) * 4 + (r & 3)) * 2 + ((r >> 2) & 1));
        cpa4(sV + wv * 4, &vb[(size_t)(kt0 + r) * D3 + d]);
    }
}

__global__ __launch_bounds__(256) void attn_mma(const float* __restrict__ qkv,
                                                const float* __restrict__ x,
                                                float* __restrict__ x1) {
    extern __shared__ uint32_t smA[];
    uint32_t smb = smem_u32(smA);

    int tid = threadIdx.x, lane = tid & 31, w = tid >> 5;
    int gid = lane >> 2, tig = lane & 3;
    int bh = blockIdx.y;
    int b = bh >> 4, h = bh & 15;
    int q0 = blockIdx.x * 128;

    const float* qbase = qkv + (size_t)b * NN * D3 + h * DHH;
    const float* kbase = qbase + DD;
    const float* vbase = qbase + 2 * DD;

    att_cp_stage(smb, smb + ATT_OP_F * 4, kbase, vbase, 0, tid);
    CP_COMMIT();
    att_cp_stage(smb + ATT_STAGE_F * 4, smb + (ATT_STAGE_F + ATT_OP_F) * 4,
                 kbase, vbase, 64, tid);
    CP_COMMIT();

    // Q fragments (rna tf32, held for whole KV loop)
    uint32_t qa[8][4];
    {
        const float* Q0 = qbase + (size_t)(q0 + w * 16 + gid) * D3;
        const float* Q1 = Q0 + 8 * D3;
        #pragma unroll
        for (int ks = 0; ks < 8; ks++) {
            qa[ks][0] = f2tf32(Q0[ks * 8 + tig]);
            qa[ks][1] = f2tf32(Q1[ks * 8 + tig]);
            qa[ks][2] = f2tf32(Q0[ks * 8 + tig + 4]);
            qa[ks][3] = f2tf32(Q1[ks * 8 + tig + 4]);
        }
    }

    float o[8][4];
    #pragma unroll
    for (int nd = 0; nd < 8; nd++)
        #pragma unroll
        for (int q = 0; q < 4; q++) o[nd][q] = 0.0f;
    float m0 = -1e30f, m1 = -1e30f, l0 = 0.0f, l1 = 0.0f;

    const int nt = NN / 64;
    for (int kt = 0; kt < nt; kt++) {
        int s = kt % 3;
        int kn = kt + 2;
        if (kn < nt) {
            int sn = kn % 3;
            att_cp_stage(smb + sn * ATT_STAGE_F * 4,
                         smb + (sn * ATT_STAGE_F + ATT_OP_F) * 4,
                         kbase, vbase, kn * 64, tid);
        }
        CP_COMMIT();
        CP_WAIT2();
        __syncthreads();

        uint32_t* sK = smA + s * ATT_STAGE_F;
        uint32_t* sV = sK + ATT_OP_F;

        // ---- S = Q @ K^T ----
        float c[8][4];
        #pragma unroll
        for (int nf = 0; nf < 8; nf++)
            #pragma unroll
            for (int q = 0; q < 4; q++) c[nf][q] = 0.0f;
        #pragma unroll
        for (int ks = 0; ks < 8; ks++) {
            #pragma unroll
            for (int nf = 0; nf < 8; nf++) {
                uint2 bb = *(uint2*)&sK[(nf * 8 + ks) * ATT_BST + lane * 2];
                uint32_t br[2] = { RNA(bb.x), RNA(bb.y) };
                mma_tf32(c[nf], qa[ks], br);
            }
        }

        // ---- online softmax ----
        float mx0 = -1e30f, mx1 = -1e30f;
        #pragma unroll
        for (int nf = 0; nf < 8; nf++) {
            mx0 = fmaxf(mx0, fmaxf(c[nf][0], c[nf][1]));
            mx1 = fmaxf(mx1, fmaxf(c[nf][2], c[nf][3]));
        }
        mx0 = fmaxf(mx0, __shfl_xor_sync(0xffffffffu, mx0, 1));
        mx0 = fmaxf(mx0, __shfl_xor_sync(0xffffffffu, mx0, 2));
        mx1 = fmaxf(mx1, __shfl_xor_sync(0xffffffffu, mx1, 1));
        mx1 = fmaxf(mx1, __shfl_xor_sync(0xffffffffu, mx1, 2));
        float m0n = fmaxf(m0, mx0), m1n = fmaxf(m1, mx1);
        float sc0 = __expf(m0 - m0n), sc1 = __expf(m1 - m1n);
        m0 = m0n; m1 = m1n;

        float rs0 = 0.0f, rs1 = 0.0f;
        #pragma unroll
        for (int nf = 0; nf < 8; nf++) {
            c[nf][0] = __expf(c[nf][0] - m0n);
            c[nf][1] = __expf(c[nf][1] - m0n);
            c[nf][2] = __expf(c[nf][2] - m1n);
            c[nf][3] = __expf(c[nf][3] - m1n);
            rs0 += c[nf][0] + c[nf][1];
            rs1 += c[nf][2] + c[nf][3];
        }
        rs0 += __shfl_xor_sync(0xffffffffu, rs0, 1);
        rs0 += __shfl_xor_sync(0xffffffffu, rs0, 2);
        rs1 += __shfl_xor_sync(0xffffffffu, rs1, 1);
        rs1 += __shfl_xor_sync(0xffffffffu, rs1, 2);
        l0 = l0 * sc0 + rs0;
        l1 = l1 * sc1 + rs1;
        #pragma unroll
        for (int nd = 0; nd < 8; nd++) {
            o[nd][0] *= sc0; o[nd][1] *= sc0;
            o[nd][2] *= sc1; o[nd][3] *= sc1;
        }

        // ---- O += P @ V ----
        int s0l = (lane & ~3) | (tig >> 1);
        int s1l = s0l + 2;
        bool odd = (tig & 1) != 0;
        #pragma unroll
        for (int ks = 0; ks < 8; ks++) {
            float v00 = __shfl_sync(0xffffffffu, c[ks][0], s0l);
            float v01 = __shfl_sync(0xffffffffu, c[ks][1], s0l);
            float v10 = __shfl_sync(0xffffffffu, c[ks][0], s1l);
            float v11 = __shfl_sync(0xffffffffu, c[ks][1], s1l);
            float w00 = __shfl_sync(0xffffffffu, c[ks][2], s0l);
            float w01 = __shfl_sync(0xffffffffu, c[ks][3], s0l);
            float w10 = __shfl_sync(0xffffffffu, c[ks][2], s1l);
            float w11 = __shfl_sync(0xffffffffu, c[ks][3], s1l);
            uint32_t pa[4];
            pa[0] = f2tf32(odd ? v01 : v00);
            pa[1] = f2tf32(odd ? w01 : w00);
            pa[2] = f2tf32(odd ? v11 : v10);
            pa[3] = f2tf32(odd ? w11 : w10);
            #pragma unroll
            for (int nd = 0; nd < 8; nd++) {
                uint2 bb = *(uint2*)&sV[(nd * 8 + ks) * ATT_BST + lane * 2];
                uint32_t br[2] = { RNA(bb.x), RNA(bb.y) };
                mma_tf32(o[nd], pa, br);
            }
        }
        __syncthreads();
    }

    // ---- epilogue: x1 = x + attn ([B,H,N,Dh] flat == [B,N,D] flat) ----
    float i0 = 1.0f / l0, i1 = 1.0f / l1;
    size_t ob = ((size_t)bh * NN + q0 + w * 16) * DHH;
    #pragma unroll
    for (int nd = 0; nd < 8; nd++) {
        int col = nd * 8 + tig * 2;
        size_t f0 = ob + (size_t)gid * DHH + col;
        size_t f1 = f0 + 8 * DHH;
        float2 x0 = *(const float2*)&x[f0];
        float2 xx1 = *(const float2*)&x[f1];
        float2 o0, o1;
        o0.x = x0.x + o[nd][0] * i0;
        o0.y = x0.y + o[nd][1] * i0;
        o1.x = xx1.x + o[nd][2] * i1;
        o1.y = xx1.y + o[nd][3] * i1;
        *(float2*)&x1[f0] = o0;
        *(float2*)&x1[f1] = o1;
    }
}

// ---------------- block reduce helper ---------------------------------------
__device__ __forceinline__ float block_sum_256(float v) {
    __shared__ float red[8];
    #pragma unroll
    for (int o = 16; o; o >>= 1) v += __shfl_xor_sync(0xffffffffu, v, o);
    int w = threadIdx.x >> 5;
    if ((threadIdx.x & 31) == 0) red[w] = v;
    __syncthreads();
    v = red[threadIdx.x & 7];
    #pragma unroll
    for (int o = 4; o; o >>= 1) v += __shfl_xor_sync(0xffffffffu, v, o);
    __syncthreads();
    return v;
}

// ---------------- LayerNorm ---------------------------------------------------
__global__ __launch_bounds__(256) void ln_kernel(const float* __restrict__ x,
                                                 const float* __restrict__ g,
                                                 const float* __restrict__ b,
                                                 float* __restrict__ out) {
    int row = blockIdx.x;
    const float4* xr = (const float4*)(x + (size_t)row * DD);
    float4 v = xr[threadIdx.x];
    float s = v.x + v.y + v.z + v.w;
    s = block_sum_256(s);
    float mu = s * (1.0f / DD);
    float dx = v.x - mu, dy = v.y - mu, dz = v.z - mu, dw = v.w - mu;
    float vs = dx*dx + dy*dy + dz*dz + dw*dw;
    vs = block_sum_256(vs);
    float rstd = rsqrtf(vs * (1.0f / DD) + 1e-5f);
    float4 gg = ((const float4*)g)[threadIdx.x];
    float4 bb = ((const float4*)b)[threadIdx.x];
    float4 o;
    o.x = dx * rstd * gg.x + bb.x;
    o.y = dy * rstd * gg.y + bb.y;
    o.z = dz * rstd * gg.z + bb.z;
    o.w = dw * rstd * gg.w + bb.w;
    ((float4*)(out + (size_t)row * DD))[threadIdx.x] = o;
}

// ---------------- launch ------------------------------------------------------
extern "C" void kernel_launch(void* const* d_in, const int* in_sizes, int n_in,
                              void* d_out, int out_size) {
    const float* x     = (const float*)d_in[0];
    const float* w_qkv = (const float*)d_in[1];
    const float* b_qkv = (const float*)d_in[2];
    const float* ln_g  = (const float*)d_in[3];
    const float* ln_b  = (const float*)d_in[4];
    const float* w1    = (const float*)d_in[5];
    const float* b1    = (const float*)d_in[6];
    const float* w2    = (const float*)d_in[7];
    const float* b2    = (const float*)d_in[8];
    float* out = (float*)d_out;

    float *xn, *qkv, *x1, *hbuf;
    cudaGetSymbolAddress((void**)&xn,   g_xn);
    cudaGetSymbolAddress((void**)&qkv,  g_qkv);
    cudaGetSymbolAddress((void**)&x1,   g_x1);
    cudaGetSymbolAddress((void**)&hbuf, g_h);

    cudaFuncSetAttribute(gemm_mma<0>, cudaFuncAttributeMaxDynamicSharedMemorySize, GEMM_SMEM_BYTES);
    cudaFuncSetAttribute(gemm_mma<1>, cudaFuncAttributeMaxDynamicSharedMemorySize, GEMM_SMEM_BYTES);
    cudaFuncSetAttribute(gemm_mma<2>, cudaFuncAttributeMaxDynamicSharedMemorySize, GEMM_SMEM_BYTES);
    cudaFuncSetAttribute(attn_mma,    cudaFuncAttributeMaxDynamicSharedMemorySize, ATT_SMEM_BYTES);

    // 1. xn = LN(x)
    ln_kernel<<<ROWS, 256>>>(x, ln_g, ln_b, xn);
    // 2. qkv = xn @ w_qkv + b_qkv
    gemm_mma<0><<<dim3(D3 / 256, ROWS / 128), 256, GEMM_SMEM_BYTES>>>(
        xn, w_qkv, b_qkv, nullptr, qkv, ROWS, D3, DD);
    // 3+4. attention fused with residual: x1 = x + attn
    attn_mma<<<dim3(NN / 128, BB * HH), 256, ATT_SMEM_BYTES>>>(qkv, x, x1);
    // 5. xn = LN(x1)
    ln_kernel<<<ROWS, 256>>>(x1, ln_g, ln_b, xn);
    // 6. h = gelu(xn @ w1 + b1)
    gemm_mma<1><<<dim3(HID / 256, ROWS / 128), 256, GEMM_SMEM_BYTES>>>(
        xn, w1, b1, nullptr, hbuf, ROWS, HID, DD);
    // 7. out = x1 + h @ w2 + b2
    gemm_mma<2><<<dim3(DD / 256, ROWS / 128), 256, GEMM_SMEM_BYTES>>>(
        hbuf, w2, b2, x1, out, ROWS, DD, HID);
}

// round 12
// speedup vs baseline: 1.3819x; 1.3819x over previous
#include <cuda_runtime.h>
#include <cuda_bf16.h>
#include <cuda_fp16.h>
#include <math.h>
#include <stdint.h>

// Problem dims (fixed by reference)
#define BB 2
#define NN 2048
#define DD 1024
#define HH 16
#define DHH 64
#define HID 4096
#define D3 3072
#define ROWS (BB*NN)          // 4096

// ---------------- scratch (static device arrays; no allocation) -------------
__device__ __half g_xnh[ROWS * DD];       // LN output in fp16
__device__ float  g_qkv[ROWS * D3];       // qkv fp32 (attention input)
__device__ float  g_x1[ROWS * DD];        // x + attn
__device__ __half g_hh[ROWS * HID];       // MLP hidden in fp16
__device__ __half g_wqkvh[DD * D3];
__device__ __half g_w1h[DD * HID];
__device__ __half g_w2h[HID * DD];

// ======================= common helpers ======================================
__device__ __forceinline__ uint32_t smem_u32(const void* p) {
    uint32_t a;
    asm("{ .reg .u64 t; cvta.to.shared.u64 t, %1; cvt.u32.u64 %0, t; }"
        : "=r"(a) : "l"(p));
    return a;
}

__device__ __forceinline__ uint32_t f2tf32(float x) {
    uint32_t u;
    asm("cvt.rna.tf32.f32 %0, %1;" : "=r"(u) : "f"(x));
    return u;
}
#define RNA(u) ((u) + 0x1000u)

__device__ __forceinline__ void mma_tf32(float* c, const uint32_t* a, const uint32_t* b) {
    asm volatile(
        "mma.sync.aligned.m16n8k8.row.col.f32.tf32.tf32.f32 "
        "{%0,%1,%2,%3}, {%4,%5,%6,%7}, {%8,%9}, {%0,%1,%2,%3};"
        : "+f"(c[0]), "+f"(c[1]), "+f"(c[2]), "+f"(c[3])
        : "r"(a[0]), "r"(a[1]), "r"(a[2]), "r"(a[3]), "r"(b[0]), "r"(b[1]));
}

__device__ __forceinline__ void mma_f16(float* c, const uint32_t* a, const uint32_t* b) {
    asm volatile(
        "mma.sync.aligned.m16n8k16.row.col.f32.f16.f16.f32 "
        "{%0,%1,%2,%3}, {%4,%5,%6,%7}, {%8,%9}, {%0,%1,%2,%3};"
        : "+f"(c[0]), "+f"(c[1]), "+f"(c[2]), "+f"(c[3])
        : "r"(a[0]), "r"(a[1]), "r"(a[2]), "r"(a[3]), "r"(b[0]), "r"(b[1]));
}

__device__ __forceinline__ void ldsm_x4(uint32_t* r, uint32_t a) {
    asm volatile("ldmatrix.sync.aligned.m8n8.x4.shared.b16 {%0,%1,%2,%3}, [%4];"
        : "=r"(r[0]), "=r"(r[1]), "=r"(r[2]), "=r"(r[3]) : "r"(a));
}
__device__ __forceinline__ void ldsm_x4_t(uint32_t* r, uint32_t a) {
    asm volatile("ldmatrix.sync.aligned.m8n8.x4.trans.shared.b16 {%0,%1,%2,%3}, [%4];"
        : "=r"(r[0]), "=r"(r[1]), "=r"(r[2]), "=r"(r[3]) : "r"(a));
}

__device__ __forceinline__ void cpa4(uint32_t dst, const float* src) {
    asm volatile("cp.async.ca.shared.global [%0], [%1], 4;" :: "r"(dst), "l"(src));
}
__device__ __forceinline__ void cpa16h(uint32_t dst, const __half* src) {
    asm volatile("cp.async.cg.shared.global [%0], [%1], 16;" :: "r"(dst), "l"(src));
}
#define CP_COMMIT() asm volatile("cp.async.commit_group;" ::: "memory")
#define CP_WAIT2()  asm volatile("cp.async.wait_group 2;" ::: "memory")

// ======================= fp16 mma GEMM =======================================
// C[M,N] = A[M,K] @ W[K,N] + bias; A,W fp16; EPI: 0 bias->f32, 1 gelu->f16,
// 2 bias+res->f32. CTA tile 128x128x32, 256 threads (8 warps 2Mx4N),
// warp tile 64x32 (MF=4,NF=4), mma m16n8k16. 3-stage cp.async pipeline.
// SMEM: A [128][KPAD_H=40] halves, B [32][NPAD_H=136] halves.

#define KPAD_H 40
#define NPAD_H 136
#define A_ST_B (128 * KPAD_H * 2)        // 10240 B
#define B_ST_B (32 * NPAD_H * 2)         // 8704 B
#define STAGE_B (A_ST_B + B_ST_B)        // 18944 B
#define GEMM_SMEM_BYTES (3 * STAGE_B)    // 56832 B

__device__ __forceinline__ void gemm_cp_stage(uint32_t sA, uint32_t sB,
                                              const __half* __restrict__ A,
                                              const __half* __restrict__ W,
                                              int K, int N, int row0, int col0,
                                              int k0, int tid) {
    // A: 128 rows x 4 chunks(8 halves) = 512
    #pragma unroll
    for (int l = 0; l < 2; l++) {
        int c = tid + l * 256;
        int r = c >> 2;
        int kc = c & 3;
        cpa16h(sA + (uint32_t)(r * KPAD_H + kc * 8) * 2,
               &A[(size_t)(row0 + r) * K + k0 + kc * 8]);
    }
    // B: 32 k-rows x 16 chunks = 512
    #pragma unroll
    for (int l = 0; l < 2; l++) {
        int c = tid + l * 256;
        int kr = c >> 4;
        int nc = c & 15;
        cpa16h(sB + (uint32_t)(kr * NPAD_H + nc * 8) * 2,
               &W[(size_t)(k0 + kr) * N + col0 + nc * 8]);
    }
}

template<int EPI>
__global__ __launch_bounds__(256) void gemm_h(const __half* __restrict__ A,
                                              const __half* __restrict__ W,
                                              const float* __restrict__ bias,
                                              const float* __restrict__ res,
                                              void* __restrict__ Cv,
                                              int M, int N, int K) {
    extern __shared__ char smc[];
    uint32_t smb = smem_u32(smc);

    int tid = threadIdx.x;
    int lane = tid & 31, wid = tid >> 5;
    int warpM = wid & 1, warpN = wid >> 1;     // 2 x 4
    int gid = lane >> 2, tig = lane & 3;
    int lt = lane >> 3, li = lane & 7;         // ldmatrix tile / row-in-tile
    int row0 = blockIdx.y * 128, col0 = blockIdx.x * 128;

    float c[4][4][4];
    #pragma unroll
    for (int mf = 0; mf < 4; mf++)
        #pragma unroll
        for (int nf = 0; nf < 4; nf++)
            #pragma unroll
            for (int q = 0; q < 4; q++) c[mf][nf][q] = 0.0f;

    int nk = K / 32;
    gemm_cp_stage(smb, smb + A_ST_B, A, W, K, N, row0, col0, 0, tid);
    CP_COMMIT();
    gemm_cp_stage(smb + STAGE_B, smb + STAGE_B + A_ST_B,
                  A, W, K, N, row0, col0, 32, tid);
    CP_COMMIT();

    for (int kt = 0; kt < nk; kt++) {
        int s = kt % 3;
        int kn = kt + 2;
        if (kn < nk) {
            int sn = kn % 3;
            gemm_cp_stage(smb + sn * STAGE_B, smb + sn * STAGE_B + A_ST_B,
                          A, W, K, N, row0, col0, kn * 32, tid);
        }
        CP_COMMIT();
        CP_WAIT2();
        __syncthreads();

        uint32_t sA = smb + s * STAGE_B;
        uint32_t sB = sA + A_ST_B;
        #pragma unroll
        for (int ss = 0; ss < 2; ss++) {      // two k16 steps
            uint32_t a[4][4], b[2][4];
            #pragma unroll
            for (int mf = 0; mf < 4; mf++) {
                // A tile: rows warpM*64+mf*16+(lt&1)*8+li, k = ss*16+(lt>>1)*8
                int rowA = warpM * 64 + mf * 16 + (lt & 1) * 8 + li;
                int koff = ss * 16 + (lt >> 1) * 8;
                ldsm_x4(a[mf], sA + (uint32_t)(rowA * KPAD_H + koff) * 2);
            }
            #pragma unroll
            for (int p = 0; p < 2; p++) {
                // B tiles (trans): k = ss*16+(lt&1)*8+li, n = warpN*32+p*16+(lt>>1)*8
                int krow = ss * 16 + (lt & 1) * 8 + li;
                int ncol = warpN * 32 + p * 16 + (lt >> 1) * 8;
                ldsm_x4_t(b[p], sB + (uint32_t)(krow * NPAD_H + ncol) * 2);
            }
            #pragma unroll
            for (int mf = 0; mf < 4; mf++) {
                mma_f16(c[mf][0], a[mf], &b[0][0]);
                mma_f16(c[mf][1], a[mf], &b[0][2]);
                mma_f16(c[mf][2], a[mf], &b[1][0]);
                mma_f16(c[mf][3], a[mf], &b[1][2]);
            }
        }
        __syncthreads();
    }

    #pragma unroll
    for (int mf = 0; mf < 4; mf++) {
        #pragma unroll
        for (int nf = 0; nf < 4; nf++) {
            int col = col0 + warpN * 32 + nf * 8 + tig * 2;
            float b0 = bias[col], b1 = bias[col + 1];
            #pragma unroll
            for (int h = 0; h < 2; h++) {
                int row = row0 + warpM * 64 + mf * 16 + gid + h * 8;
                float v0 = c[mf][nf][h * 2 + 0] + b0;
                float v1 = c[mf][nf][h * 2 + 1] + b1;
                if (EPI == 1) {
                    v0 = 0.5f * v0 * (1.0f + erff(v0 * 0.70710678118654752f));
                    v1 = 0.5f * v1 * (1.0f + erff(v1 * 0.70710678118654752f));
                    __half2 hv = __floats2half2_rn(v0, v1);
                    *(__half2*)((__half*)Cv + (size_t)row * N + col) = hv;
                } else {
                    if (EPI == 2) {
                        float2 rr = *(const float2*)&res[(size_t)row * N + col];
                        v0 += rr.x; v1 += rr.y;
                    }
                    float2 o; o.x = v0; o.y = v1;
                    *(float2*)((float*)Cv + (size_t)row * N + col) = o;
                }
            }
        }
    }
}

// ---------------- fp32 -> fp16 conversion -----------------------------------
__global__ __launch_bounds__(256) void cvt_kernel(const float* __restrict__ in,
                                                  __half* __restrict__ out, int n) {
    int i = (blockIdx.x * 256 + threadIdx.x) * 4;
    if (i < n) {
        float4 v = *(const float4*)&in[i];
        __half2 h0 = __floats2half2_rn(v.x, v.y);
        __half2 h1 = __floats2half2_rn(v.z, v.w);
        uint2 u; u.x = *(uint32_t*)&h0; u.y = *(uint32_t*)&h1;
        *(uint2*)&out[i] = u;
    }
}

// ======================= mma.sync tf32 flash attention =======================
// (unchanged from R10 — qkv stays fp32)
#define ATT_BST 66
#define ATT_OP_F (64 * ATT_BST)
#define ATT_STAGE_F (2 * ATT_OP_F)
#define ATT_SMEM_BYTES (3 * ATT_STAGE_F * 4)   // 101376 B

__device__ __forceinline__ void att_cp_stage(uint32_t sK, uint32_t sV,
                                             const float* __restrict__ kb,
                                             const float* __restrict__ vb,
                                             int kt0, int tid) {
    #pragma unroll
    for (int l = 0; l < 16; l++) {
        int f = tid + l * 256;
        int r = f >> 6;
        int d = f & 63;
        uint32_t wk = (uint32_t)(((r >> 3) * 8 + (d >> 3)) * ATT_BST
                      + ((r & 7) * 4 + (d & 3)) * 2 + ((d >> 2) & 1));
        cpa4(sK + wk * 4, &kb[(size_t)(kt0 + r) * D3 + d]);
        uint32_t wv = (uint32_t)(((d >> 3) * 8 + (r >> 3)) * ATT_BST
                      + ((d & 7) * 4 + (r & 3)) * 2 + ((r >> 2) & 1));
        cpa4(sV + wv * 4, &vb[(size_t)(kt0 + r) * D3 + d]);
    }
}

__global__ __launch_bounds__(256) void attn_mma(const float* __restrict__ qkv,
                                                const float* __restrict__ x,
                                                float* __restrict__ x1) {
    extern __shared__ uint32_t smA[];
    uint32_t smb = smem_u32(smA);

    int tid = threadIdx.x, lane = tid & 31, w = tid >> 5;
    int gid = lane >> 2, tig = lane & 3;
    int bh = blockIdx.y;
    int b = bh >> 4, h = bh & 15;
    int q0 = blockIdx.x * 128;

    const float* qbase = qkv + (size_t)b * NN * D3 + h * DHH;
    const float* kbase = qbase + DD;
    const float* vbase = qbase + 2 * DD;

    att_cp_stage(smb, smb + ATT_OP_F * 4, kbase, vbase, 0, tid);
    CP_COMMIT();
    att_cp_stage(smb + ATT_STAGE_F * 4, smb + (ATT_STAGE_F + ATT_OP_F) * 4,
                 kbase, vbase, 64, tid);
    CP_COMMIT();

    uint32_t qa[8][4];
    {
        const float* Q0 = qbase + (size_t)(q0 + w * 16 + gid) * D3;
        const float* Q1 = Q0 + 8 * D3;
        #pragma unroll
        for (int ks = 0; ks < 8; ks++) {
            qa[ks][0] = f2tf32(Q0[ks * 8 + tig]);
            qa[ks][1] = f2tf32(Q1[ks * 8 + tig]);
            qa[ks][2] = f2tf32(Q0[ks * 8 + tig + 4]);
            qa[ks][3] = f2tf32(Q1[ks * 8 + tig + 4]);
        }
    }

    float o[8][4];
    #pragma unroll
    for (int nd = 0; nd < 8; nd++)
        #pragma unroll
        for (int q = 0; q < 4; q++) o[nd][q] = 0.0f;
    float m0 = -1e30f, m1 = -1e30f, l0 = 0.0f, l1 = 0.0f;

    const int nt = NN / 64;
    for (int kt = 0; kt < nt; kt++) {
        int s = kt % 3;
        int kn = kt + 2;
        if (kn < nt) {
            int sn = kn % 3;
            att_cp_stage(smb + sn * ATT_STAGE_F * 4,
                         smb + (sn * ATT_STAGE_F + ATT_OP_F) * 4,
                         kbase, vbase, kn * 64, tid);
        }
        CP_COMMIT();
        CP_WAIT2();
        __syncthreads();

        uint32_t* sK = smA + s * ATT_STAGE_F;
        uint32_t* sV = sK + ATT_OP_F;

        float c[8][4];
        #pragma unroll
        for (int nf = 0; nf < 8; nf++)
            #pragma unroll
            for (int q = 0; q < 4; q++) c[nf][q] = 0.0f;
        #pragma unroll
        for (int ks = 0; ks < 8; ks++) {
            #pragma unroll
            for (int nf = 0; nf < 8; nf++) {
                uint2 bb = *(uint2*)&sK[(nf * 8 + ks) * ATT_BST + lane * 2];
                uint32_t br[2] = { RNA(bb.x), RNA(bb.y) };
                mma_tf32(c[nf], qa[ks], br);
            }
        }

        float mx0 = -1e30f, mx1 = -1e30f;
        #pragma unroll
        for (int nf = 0; nf < 8; nf++) {
            mx0 = fmaxf(mx0, fmaxf(c[nf][0], c[nf][1]));
            mx1 = fmaxf(mx1, fmaxf(c[nf][2], c[nf][3]));
        }
        mx0 = fmaxf(mx0, __shfl_xor_sync(0xffffffffu, mx0, 1));
        mx0 = fmaxf(mx0, __shfl_xor_sync(0xffffffffu, mx0, 2));
        mx1 = fmaxf(mx1, __shfl_xor_sync(0xffffffffu, mx1, 1));
        mx1 = fmaxf(mx1, __shfl_xor_sync(0xffffffffu, mx1, 2));
        float m0n = fmaxf(m0, mx0), m1n = fmaxf(m1, mx1);
        float sc0 = __expf(m0 - m0n), sc1 = __expf(m1 - m1n);
        m0 = m0n; m1 = m1n;

        float rs0 = 0.0f, rs1 = 0.0f;
        #pragma unroll
        for (int nf = 0; nf < 8; nf++) {
            c[nf][0] = __expf(c[nf][0] - m0n);
            c[nf][1] = __expf(c[nf][1] - m0n);
            c[nf][2] = __expf(c[nf][2] - m1n);
            c[nf][3] = __expf(c[nf][3] - m1n);
            rs0 += c[nf][0] + c[nf][1];
            rs1 += c[nf][2] + c[nf][3];
        }
        rs0 += __shfl_xor_sync(0xffffffffu, rs0, 1);
        rs0 += __shfl_xor_sync(0xffffffffu, rs0, 2);
        rs1 += __shfl_xor_sync(0xffffffffu, rs1, 1);
        rs1 += __shfl_xor_sync(0xffffffffu, rs1, 2);
        l0 = l0 * sc0 + rs0;
        l1 = l1 * sc1 + rs1;
        #pragma unroll
        for (int nd = 0; nd < 8; nd++) {
            o[nd][0] *= sc0; o[nd][1] *= sc0;
            o[nd][2] *= sc1; o[nd][3] *= sc1;
        }

        int s0l = (lane & ~3) | (tig >> 1);
        int s1l = s0l + 2;
        bool odd = (tig & 1) != 0;
        #pragma unroll
        for (int ks = 0; ks < 8; ks++) {
            float v00 = __shfl_sync(0xffffffffu, c[ks][0], s0l);
            float v01 = __shfl_sync(0xffffffffu, c[ks][1], s0l);
            float v10 = __shfl_sync(0xffffffffu, c[ks][0], s1l);
            float v11 = __shfl_sync(0xffffffffu, c[ks][1], s1l);
            float w00 = __shfl_sync(0xffffffffu, c[ks][2], s0l);
            float w01 = __shfl_sync(0xffffffffu, c[ks][3], s0l);
            float w10 = __shfl_sync(0xffffffffu, c[ks][2], s1l);
            float w11 = __shfl_sync(0xffffffffu, c[ks][3], s1l);
            uint32_t pa[4];
            pa[0] = f2tf32(odd ? v01 : v00);
            pa[1] = f2tf32(odd ? w01 : w00);
            pa[2] = f2tf32(odd ? v11 : v10);
            pa[3] = f2tf32(odd ? w11 : w10);
            #pragma unroll
            for (int nd = 0; nd < 8; nd++) {
                uint2 bb = *(uint2*)&sV[(nd * 8 + ks) * ATT_BST + lane * 2];
                uint32_t br[2] = { RNA(bb.x), RNA(bb.y) };
                mma_tf32(o[nd], pa, br);
            }
        }
        __syncthreads();
    }

    float i0 = 1.0f / l0, i1 = 1.0f / l1;
    size_t ob = ((size_t)bh * NN + q0 + w * 16) * DHH;
    #pragma unroll
    for (int nd = 0; nd < 8; nd++) {
        int col = nd * 8 + tig * 2;
        size_t f0 = ob + (size_t)gid * DHH + col;
        size_t f1 = f0 + 8 * DHH;
        float2 x0 = *(const float2*)&x[f0];
        float2 xx1 = *(const float2*)&x[f1];
        float2 o0, o1;
        o0.x = x0.x + o[nd][0] * i0;
        o0.y = x0.y + o[nd][1] * i0;
        o1.x = xx1.x + o[nd][2] * i1;
        o1.y = xx1.y + o[nd][3] * i1;
        *(float2*)&x1[f0] = o0;
        *(float2*)&x1[f1] = o1;
    }
}

// ---------------- block reduce helper ---------------------------------------
__device__ __forceinline__ float block_sum_256(float v) {
    __shared__ float red[8];
    #pragma unroll
    for (int o = 16; o; o >>= 1) v += __shfl_xor_sync(0xffffffffu, v, o);
    int w = threadIdx.x >> 5;
    if ((threadIdx.x & 31) == 0) red[w] = v;
    __syncthreads();
    v = red[threadIdx.x & 7];
    #pragma unroll
    for (int o = 4; o; o >>= 1) v += __shfl_xor_sync(0xffffffffu, v, o);
    __syncthreads();
    return v;
}

// ---------------- LayerNorm (fp32 in, fp16 out) -------------------------------
__global__ __launch_bounds__(256) void ln_kernel(const float* __restrict__ x,
                                                 const float* __restrict__ g,
                                                 const float* __restrict__ b,
                                                 __half* __restrict__ out) {
    int row = blockIdx.x;
    const float4* xr = (const float4*)(x + (size_t)row * DD);
    float4 v = xr[threadIdx.x];
    float s = v.x + v.y + v.z + v.w;
    s = block_sum_256(s);
    float mu = s * (1.0f / DD);
    float dx = v.x - mu, dy = v.y - mu, dz = v.z - mu, dw = v.w - mu;
    float vs = dx*dx + dy*dy + dz*dz + dw*dw;
    vs = block_sum_256(vs);
    float rstd = rsqrtf(vs * (1.0f / DD) + 1e-5f);
    float4 gg = ((const float4*)g)[threadIdx.x];
    float4 bb = ((const float4*)b)[threadIdx.x];
    __half2 h0 = __floats2half2_rn(dx * rstd * gg.x + bb.x, dy * rstd * gg.y + bb.y);
    __half2 h1 = __floats2half2_rn(dz * rstd * gg.z + bb.z, dw * rstd * gg.w + bb.w);
    uint2 u; u.x = *(uint32_t*)&h0; u.y = *(uint32_t*)&h1;
    *(uint2*)&out[(size_t)row * DD + threadIdx.x * 4] = u;
}

// ---------------- launch ------------------------------------------------------
extern "C" void kernel_launch(void* const* d_in, const int* in_sizes, int n_in,
                              void* d_out, int out_size) {
    const float* x     = (const float*)d_in[0];
    const float* w_qkv = (const float*)d_in[1];
    const float* b_qkv = (const float*)d_in[2];
    const float* ln_g  = (const float*)d_in[3];
    const float* ln_b  = (const float*)d_in[4];
    const float* w1    = (const float*)d_in[5];
    const float* b1    = (const float*)d_in[6];
    const float* w2    = (const float*)d_in[7];
    const float* b2    = (const float*)d_in[8];
    float* out = (float*)d_out;

    __half *xnh, *hh, *wqkvh, *w1h, *w2h;
    float *qkv, *x1;
    cudaGetSymbolAddress((void**)&xnh,   g_xnh);
    cudaGetSymbolAddress((void**)&qkv,   g_qkv);
    cudaGetSymbolAddress((void**)&x1,    g_x1);
    cudaGetSymbolAddress((void**)&hh,    g_hh);
    cudaGetSymbolAddress((void**)&wqkvh, g_wqkvh);
    cudaGetSymbolAddress((void**)&w1h,   g_w1h);
    cudaGetSymbolAddress((void**)&w2h,   g_w2h);

    cudaFuncSetAttribute(gemm_h<0>, cudaFuncAttributeMaxDynamicSharedMemorySize, GEMM_SMEM_BYTES);
    cudaFuncSetAttribute(gemm_h<1>, cudaFuncAttributeMaxDynamicSharedMemorySize, GEMM_SMEM_BYTES);
    cudaFuncSetAttribute(gemm_h<2>, cudaFuncAttributeMaxDynamicSharedMemorySize, GEMM_SMEM_BYTES);
    cudaFuncSetAttribute(attn_mma,  cudaFuncAttributeMaxDynamicSharedMemorySize, ATT_SMEM_BYTES);

    // 0. weights -> fp16
    cvt_kernel<<<(DD * D3) / 1024, 256>>>(w_qkv, wqkvh, DD * D3);
    cvt_kernel<<<(DD * HID) / 1024, 256>>>(w1, w1h, DD * HID);
    cvt_kernel<<<(HID * DD) / 1024, 256>>>(w2, w2h, HID * DD);

    // 1. xnh = LN(x) in fp16
    ln_kernel<<<ROWS, 256>>>(x, ln_g, ln_b, xnh);
    // 2. qkv = xnh @ wqkv + b_qkv (fp32 out)
    gemm_h<0><<<dim3(D3 / 128, ROWS / 128), 256, GEMM_SMEM_BYTES>>>(
        xnh, wqkvh, b_qkv, nullptr, qkv, ROWS, D3, DD);
    // 3+4. attention fused with residual: x1 = x + attn
    attn_mma<<<dim3(NN / 128, BB * HH), 256, ATT_SMEM_BYTES>>>(qkv, x, x1);
    // 5. xnh = LN(x1)
    ln_kernel<<<ROWS, 256>>>(x1, ln_g, ln_b, xnh);
    // 6. hh = gelu(xnh @ w1 + b1) (fp16 out)
    gemm_h<1><<<dim3(HID / 128, ROWS / 128), 256, GEMM_SMEM_BYTES>>>(
        xnh, w1h, b1, nullptr, hh, ROWS, HID, DD);
    // 7. out = x1 + hh @ w2 + b2 (fp32 out)
    gemm_h<2><<<dim3(DD / 128, ROWS / 128), 256, GEMM_SMEM_BYTES>>>(
        hh, w2h, b2, x1, out, ROWS, DD, HID);
}

// round 17
// speedup vs baseline: 2.0284x; 1.4679x over previous
#include <cuda_runtime.h>
#include <cuda_bf16.h>
#include <cuda_fp16.h>
#include <math.h>
#include <stdint.h>

// Problem dims (fixed by reference)
#define BB 2
#define NN 2048
#define DD 1024
#define HH 16
#define DHH 64
#define HID 4096
#define D3 3072
#define ROWS (BB*NN)          // 4096

// ---------------- scratch (static device arrays; no allocation) -------------
__device__ __half g_xnh[ROWS * DD];       // LN output in fp16
__device__ __half g_qkvh[ROWS * D3];      // qkv fp16
__device__ float  g_x1[ROWS * DD];        // x + attn
__device__ __half g_hh[ROWS * HID];       // MLP hidden in fp16
__device__ __half g_wqkvh[DD * D3];
__device__ __half g_w1h[DD * HID];
__device__ __half g_w2h[HID * DD];

// ======================= common helpers ======================================
__device__ __forceinline__ uint32_t smem_u32(const void* p) {
    uint32_t a;
    asm("{ .reg .u64 t; cvta.to.shared.u64 t, %1; cvt.u32.u64 %0, t; }"
        : "=r"(a) : "l"(p));
    return a;
}

__device__ __forceinline__ void mma_f16(float* c, const uint32_t* a, const uint32_t* b) {
    asm volatile(
        "mma.sync.aligned.m16n8k16.row.col.f32.f16.f16.f32 "
        "{%0,%1,%2,%3}, {%4,%5,%6,%7}, {%8,%9}, {%0,%1,%2,%3};"
        : "+f"(c[0]), "+f"(c[1]), "+f"(c[2]), "+f"(c[3])
        : "r"(a[0]), "r"(a[1]), "r"(a[2]), "r"(a[3]), "r"(b[0]), "r"(b[1]));
}

__device__ __forceinline__ void ldsm_x4(uint32_t* r, uint32_t a) {
    asm volatile("ldmatrix.sync.aligned.m8n8.x4.shared.b16 {%0,%1,%2,%3}, [%4];"
        : "=r"(r[0]), "=r"(r[1]), "=r"(r[2]), "=r"(r[3]) : "r"(a));
}
__device__ __forceinline__ void ldsm_x4_t(uint32_t* r, uint32_t a) {
    asm volatile("ldmatrix.sync.aligned.m8n8.x4.trans.shared.b16 {%0,%1,%2,%3}, [%4];"
        : "=r"(r[0]), "=r"(r[1]), "=r"(r[2]), "=r"(r[3]) : "r"(a));
}

__device__ __forceinline__ void cpa16h(uint32_t dst, const __half* src) {
    asm volatile("cp.async.cg.shared.global [%0], [%1], 16;" :: "r"(dst), "l"(src));
}
#define CP_COMMIT() asm volatile("cp.async.commit_group;" ::: "memory")
#define CP_WAIT2()  asm volatile("cp.async.wait_group 2;" ::: "memory")

__device__ __forceinline__ uint32_t pack_h2(float a, float b) {
    __half2 h = __floats2half2_rn(a, b);
    return *(uint32_t*)&h;
}

// ======================= fp16 mma GEMM =======================================
// C[M,N] = A[M,K] @ W[K,N] + bias; A,W fp16.
// EPI: 0 bias->f16, 1 gelu->f16, 2 bias+res->f32.
// CTA tile 128x128x32, 256 threads (8 warps 2Mx4N), warp tile 64x32,
// mma m16n8k16. 3-stage cp.async pipeline.

#define KPAD_H 40
#define NPAD_H 136
#define A_ST_B (128 * KPAD_H * 2)        // 10240 B
#define B_ST_B (32 * NPAD_H * 2)         // 8704 B
#define STAGE_B (A_ST_B + B_ST_B)        // 18944 B
#define GEMM_SMEM_BYTES (3 * STAGE_B)    // 56832 B

__device__ __forceinline__ void gemm_cp_stage(uint32_t sA, uint32_t sB,
                                              const __half* __restrict__ A,
                                              const __half* __restrict__ W,
                                              int K, int N, int row0, int col0,
                                              int k0, int tid) {
    #pragma unroll
    for (int l = 0; l < 2; l++) {
        int c = tid + l * 256;
        int r = c >> 2;
        int kc = c & 3;
        cpa16h(sA + (uint32_t)(r * KPAD_H + kc * 8) * 2,
               &A[(size_t)(row0 + r) * K + k0 + kc * 8]);
    }
    #pragma unroll
    for (int l = 0; l < 2; l++) {
        int c = tid + l * 256;
        int kr = c >> 4;
        int nc = c & 15;
        cpa16h(sB + (uint32_t)(kr * NPAD_H + nc * 8) * 2,
               &W[(size_t)(k0 + kr) * N + col0 + nc * 8]);
    }
}

template<int EPI>
__global__ __launch_bounds__(256) void gemm_h(const __half* __restrict__ A,
                                              const __half* __restrict__ W,
                                              const float* __restrict__ bias,
                                              const float* __restrict__ res,
                                              void* __restrict__ Cv,
                                              int M, int N, int K) {
    extern __shared__ char smc[];
    uint32_t smb = smem_u32(smc);

    int tid = threadIdx.x;
    int lane = tid & 31, wid = tid >> 5;
    int warpM = wid & 1, warpN = wid >> 1;
    int gid = lane >> 2, tig = lane & 3;
    int lt = lane >> 3, li = lane & 7;
    int row0 = blockIdx.y * 128, col0 = blockIdx.x * 128;

    float c[4][4][4];
    #pragma unroll
    for (int mf = 0; mf < 4; mf++)
        #pragma unroll
        for (int nf = 0; nf < 4; nf++)
            #pragma unroll
            for (int q = 0; q < 4; q++) c[mf][nf][q] = 0.0f;

    int nk = K / 32;
    gemm_cp_stage(smb, smb + A_ST_B, A, W, K, N, row0, col0, 0, tid);
    CP_COMMIT();
    gemm_cp_stage(smb + STAGE_B, smb + STAGE_B + A_ST_B,
                  A, W, K, N, row0, col0, 32, tid);
    CP_COMMIT();

    for (int kt = 0; kt < nk; kt++) {
        int s = kt % 3;
        int kn = kt + 2;
        if (kn < nk) {
            int sn = kn % 3;
            gemm_cp_stage(smb + sn * STAGE_B, smb + sn * STAGE_B + A_ST_B,
                          A, W, K, N, row0, col0, kn * 32, tid);
        }
        CP_COMMIT();
        CP_WAIT2();
        __syncthreads();

        uint32_t sA = smb + s * STAGE_B;
        uint32_t sB = sA + A_ST_B;
        #pragma unroll
        for (int ss = 0; ss < 2; ss++) {
            uint32_t a[4][4], b[2][4];
            #pragma unroll
            for (int mf = 0; mf < 4; mf++) {
                int rowA = warpM * 64 + mf * 16 + (lt & 1) * 8 + li;
                int koff = ss * 16 + (lt >> 1) * 8;
                ldsm_x4(a[mf], sA + (uint32_t)(rowA * KPAD_H + koff) * 2);
            }
            #pragma unroll
            for (int p = 0; p < 2; p++) {
                int krow = ss * 16 + (lt & 1) * 8 + li;
                int ncol = warpN * 32 + p * 16 + (lt >> 1) * 8;
                ldsm_x4_t(b[p], sB + (uint32_t)(krow * NPAD_H + ncol) * 2);
            }
            #pragma unroll
            for (int mf = 0; mf < 4; mf++) {
                mma_f16(c[mf][0], a[mf], &b[0][0]);
                mma_f16(c[mf][1], a[mf], &b[0][2]);
                mma_f16(c[mf][2], a[mf], &b[1][0]);
                mma_f16(c[mf][3], a[mf], &b[1][2]);
            }
        }
        __syncthreads();
    }

    #pragma unroll
    for (int mf = 0; mf < 4; mf++) {
        #pragma unroll
        for (int nf = 0; nf < 4; nf++) {
            int col = col0 + warpN * 32 + nf * 8 + tig * 2;
            float b0 = bias[col], b1 = bias[col + 1];
            #pragma unroll
            for (int h = 0; h < 2; h++) {
                int row = row0 + warpM * 64 + mf * 16 + gid + h * 8;
                float v0 = c[mf][nf][h * 2 + 0] + b0;
                float v1 = c[mf][nf][h * 2 + 1] + b1;
                if (EPI == 1) {
                    v0 = 0.5f * v0 * (1.0f + erff(v0 * 0.70710678118654752f));
                    v1 = 0.5f * v1 * (1.0f + erff(v1 * 0.70710678118654752f));
                }
                if (EPI == 0 || EPI == 1) {
                    __half2 hv = __floats2half2_rn(v0, v1);
                    *(__half2*)((__half*)Cv + (size_t)row * N + col) = hv;
                } else {
                    float2 rr = *(const float2*)&res[(size_t)row * N + col];
                    v0 += rr.x; v1 += rr.y;
                    float2 o; o.x = v0; o.y = v1;
                    *(float2*)((float*)Cv + (size_t)row * N + col) = o;
                }
            }
        }
    }
}

// ---------------- fp32 -> fp16 conversion -----------------------------------
__global__ __launch_bounds__(256) void cvt_kernel(const float* __restrict__ in,
                                                  __half* __restrict__ out, int n) {
    int i = (blockIdx.x * 256 + threadIdx.x) * 4;
    if (i < n) {
        float4 v = *(const float4*)&in[i];
        __half2 h0 = __floats2half2_rn(v.x, v.y);
        __half2 h1 = __floats2half2_rn(v.z, v.w);
        uint2 u; u.x = *(uint32_t*)&h0; u.y = *(uint32_t*)&h1;
        *(uint2*)&out[i] = u;
    }
}

// ======================= fp16 mma flash attention ============================
// CTA: 128 q-rows x 1 head; 8 warps x 16 rows; key tile 64; Dh=64.
// Q staged once; K/V 3-stage cp.async pipeline. All operands fp16,
// fp32 accumulate. P->A fragment is a pure half2 pack (layout identity).
// Fused epilogue: x1 = x + attn (raw-reshape flat add).

#define AP 72                             // padded row halves (dh 64 + 8)
#define Q_B (128 * AP * 2)                // 18432 B
#define KV_B (64 * AP * 2)                // 9216 B per operand
#define ATT_STAGE_B (2 * KV_B)            // 18432 B
#define ATT_SMEM_BYTES (Q_B + 3 * ATT_STAGE_B)   // 73728 B

__device__ __forceinline__ void att_cp_kv(uint32_t sK, uint32_t sV,
                                          const __half* __restrict__ kb,
                                          const __half* __restrict__ vb,
                                          int kt0, int tid) {
    #pragma unroll
    for (int l = 0; l < 2; l++) {
        int c = tid + l * 256;           // 0..511
        int r = c >> 3;                  // key row 0..63
        int kc = c & 7;                  // 16B chunk over dh
        cpa16h(sK + (uint32_t)(r * AP + kc * 8) * 2,
               &kb[(size_t)(kt0 + r) * D3 + kc * 8]);
        cpa16h(sV + (uint32_t)(r * AP + kc * 8) * 2,
               &vb[(size_t)(kt0 + r) * D3 + kc * 8]);
    }
}

__global__ __launch_bounds__(256) void attn_h(const __half* __restrict__ qkv,
                                              const float* __restrict__ x,
                                              float* __restrict__ x1) {
    extern __shared__ char smc[];
    uint32_t smb = smem_u32(smc);
    uint32_t sQ = smb;
    uint32_t sKV0 = smb + Q_B;

    int tid = threadIdx.x, lane = tid & 31, w = tid >> 5;
    int gid = lane >> 2, tig = lane & 3;
    int lt = lane >> 3, li = lane & 7;
    int bh = blockIdx.y;
    int b = bh >> 4, h = bh & 15;
    int q0 = blockIdx.x * 128;

    const __half* qb = qkv + (size_t)b * NN * D3 + h * DHH;
    const __half* kb = qb + DD;
    const __half* vb = qb + 2 * DD;

    // stage Q (group 0)
    #pragma unroll
    for (int l = 0; l < 4; l++) {
        int c = tid + l * 256;           // 0..1023
        int r = c >> 3;                  // q row 0..127
        int kc = c & 7;
        cpa16h(sQ + (uint32_t)(r * AP + kc * 8) * 2,
               &qb[(size_t)(q0 + r) * D3 + kc * 8]);
    }
    CP_COMMIT();
    att_cp_kv(sKV0, sKV0 + KV_B, kb, vb, 0, tid);
    CP_COMMIT();
    att_cp_kv(sKV0 + ATT_STAGE_B, sKV0 + ATT_STAGE_B + KV_B, kb, vb, 64, tid);
    CP_COMMIT();

    // wait for Q (leaves 2 KV groups in flight), build Q fragments
    CP_WAIT2();
    __syncthreads();
    uint32_t qa[4][4];
    #pragma unroll
    for (int ks = 0; ks < 4; ks++) {
        int rowA = w * 16 + (lt & 1) * 8 + li;
        int koff = ks * 16 + (lt >> 1) * 8;
        ldsm_x4(qa[ks], sQ + (uint32_t)(rowA * AP + koff) * 2);
    }

    float o[8][4];
    #pragma unroll
    for (int nd = 0; nd < 8; nd++)
        #pragma unroll
        for (int q = 0; q < 4; q++) o[nd][q] = 0.0f;
    float m0 = -1e30f, m1 = -1e30f, l0 = 0.0f, l1 = 0.0f;

    const int nt = NN / 64;
    for (int kt = 0; kt < nt; kt++) {
        int s = kt % 3;
        int kn = kt + 2;
        if (kn < nt) {
            int sn = kn % 3;
            att_cp_kv(sKV0 + sn * ATT_STAGE_B, sKV0 + sn * ATT_STAGE_B + KV_B,
                      kb, vb, kn * 64, tid);
        }
        CP_COMMIT();
        CP_WAIT2();
        __syncthreads();

        uint32_t sK = sKV0 + s * ATT_STAGE_B;
        uint32_t sV = sK + KV_B;

        // ---- S = Q @ K^T  (16 q x 64 keys per warp) ----
        float c[8][4];
        #pragma unroll
        for (int nf = 0; nf < 8; nf++)
            #pragma unroll
            for (int q = 0; q < 4; q++) c[nf][q] = 0.0f;
        #pragma unroll
        for (int ks = 0; ks < 4; ks++) {
            #pragma unroll
            for (int np = 0; np < 4; np++) {
                int key = np * 16 + (lt >> 1) * 8 + li;
                int dh  = ks * 16 + (lt & 1) * 8;
                uint32_t bk[4];
                ldsm_x4(bk, sK + (uint32_t)(key * AP + dh) * 2);
                mma_f16(c[np * 2],     qa[ks], &bk[0]);
                mma_f16(c[np * 2 + 1], qa[ks], &bk[2]);
            }
        }

        // ---- online softmax (rows gid / gid+8) ----
        float mx0 = -1e30f, mx1 = -1e30f;
        #pragma unroll
        for (int nf = 0; nf < 8; nf++) {
            mx0 = fmaxf(mx0, fmaxf(c[nf][0], c[nf][1]));
            mx1 = fmaxf(mx1, fmaxf(c[nf][2], c[nf][3]));
        }
        mx0 = fmaxf(mx0, __shfl_xor_sync(0xffffffffu, mx0, 1));
        mx0 = fmaxf(mx0, __shfl_xor_sync(0xffffffffu, mx0, 2));
        mx1 = fmaxf(mx1, __shfl_xor_sync(0xffffffffu, mx1, 1));
        mx1 = fmaxf(mx1, __shfl_xor_sync(0xffffffffu, mx1, 2));
        float m0n = fmaxf(m0, mx0), m1n = fmaxf(m1, mx1);
        float sc0 = __expf(m0 - m0n), sc1 = __expf(m1 - m1n);
        m0 = m0n; m1 = m1n;

        float rs0 = 0.0f, rs1 = 0.0f;
        #pragma unroll
        for (int nf = 0; nf < 8; nf++) {
            c[nf][0] = __expf(c[nf][0] - m0n);
            c[nf][1] = __expf(c[nf][1] - m0n);
            c[nf][2] = __expf(c[nf][2] - m1n);
            c[nf][3] = __expf(c[nf][3] - m1n);
            rs0 += c[nf][0] + c[nf][1];
            rs1 += c[nf][2] + c[nf][3];
        }
        rs0 += __shfl_xor_sync(0xffffffffu, rs0, 1);
        rs0 += __shfl_xor_sync(0xffffffffu, rs0, 2);
        rs1 += __shfl_xor_sync(0xffffffffu, rs1, 1);
        rs1 += __shfl_xor_sync(0xffffffffu, rs1, 2);
        l0 = l0 * sc0 + rs0;
        l1 = l1 * sc1 + rs1;
        #pragma unroll
        for (int nd = 0; nd < 8; nd++) {
            o[nd][0] *= sc0; o[nd][1] *= sc0;
            o[nd][2] *= sc1; o[nd][3] *= sc1;
        }

        // ---- O += P @ V : P fragments are direct packs of c ----
        #pragma unroll
        for (int ks = 0; ks < 4; ks++) {
            uint32_t pa[4];
            pa[0] = pack_h2(c[2 * ks][0],     c[2 * ks][1]);
            pa[1] = pack_h2(c[2 * ks][2],     c[2 * ks][3]);
            pa[2] = pack_h2(c[2 * ks + 1][0], c[2 * ks + 1][1]);
            pa[3] = pack_h2(c[2 * ks + 1][2], c[2 * ks + 1][3]);
            #pragma unroll
            for (int np = 0; np < 4; np++) {
                int krow = ks * 16 + (lt & 1) * 8 + li;
                int ncol = np * 16 + (lt >> 1) * 8;
                uint32_t bv[4];
                ldsm_x4_t(bv, sV + (uint32_t)(krow * AP + ncol) * 2);
                mma_f16(o[np * 2],     pa, &bv[0]);
                mma_f16(o[np * 2 + 1], pa, &bv[2]);
            }
        }
        __syncthreads();
    }

    // ---- epilogue: x1 = x + attn ([B,H,N,Dh] flat == [B,N,D] flat) ----
    float i0 = 1.0f / l0, i1 = 1.0f / l1;
    size_t ob = ((size_t)bh * NN + q0 + w * 16) * DHH;
    #pragma unroll
    for (int nd = 0; nd < 8; nd++) {
        int col = nd * 8 + tig * 2;
        size_t f0 = ob + (size_t)gid * DHH + col;
        size_t f1 = f0 + 8 * DHH;
        float2 x0 = *(const float2*)&x[f0];
        float2 xx1 = *(const float2*)&x[f1];
        float2 o0, o1;
        o0.x = x0.x + o[nd][0] * i0;
        o0.y = x0.y + o[nd][1] * i0;
        o1.x = xx1.x + o[nd][2] * i1;
        o1.y = xx1.y + o[nd][3] * i1;
        *(float2*)&x1[f0] = o0;
        *(float2*)&x1[f1] = o1;
    }
}

// ---------------- block reduce helper ---------------------------------------
__device__ __forceinline__ float block_sum_256(float v) {
    __shared__ float red[8];
    #pragma unroll
    for (int o = 16; o; o >>= 1) v += __shfl_xor_sync(0xffffffffu, v, o);
    int w = threadIdx.x >> 5;
    if ((threadIdx.x & 31) == 0) red[w] = v;
    __syncthreads();
    v = red[threadIdx.x & 7];
    #pragma unroll
    for (int o = 4; o; o >>= 1) v += __shfl_xor_sync(0xffffffffu, v, o);
    __syncthreads();
    return v;
}

// ---------------- LayerNorm (fp32 in, fp16 out) -------------------------------
__global__ __launch_bounds__(256) void ln_kernel(const float* __restrict__ x,
                                                 const float* __restrict__ g,
                                                 const float* __restrict__ b,
                                                 __half* __restrict__ out) {
    int row = blockIdx.x;
    const float4* xr = (const float4*)(x + (size_t)row * DD);
    float4 v = xr[threadIdx.x];
    float s = v.x + v.y + v.z + v.w;
    s = block_sum_256(s);
    float mu = s * (1.0f / DD);
    float dx = v.x - mu, dy = v.y - mu, dz = v.z - mu, dw = v.w - mu;
    float vs = dx*dx + dy*dy + dz*dz + dw*dw;
    vs = block_sum_256(vs);
    float rstd = rsqrtf(vs * (1.0f / DD) + 1e-5f);
    float4 gg = ((const float4*)g)[threadIdx.x];
    float4 bb = ((const float4*)b)[threadIdx.x];
    __half2 h0 = __floats2half2_rn(dx * rstd * gg.x + bb.x, dy * rstd * gg.y + bb.y);
    __half2 h1 = __floats2half2_rn(dz * rstd * gg.z + bb.z, dw * rstd * gg.w + bb.w);
    uint2 u; u.x = *(uint32_t*)&h0; u.y = *(uint32_t*)&h1;
    *(uint2*)&out[(size_t)row * DD + threadIdx.x * 4] = u;
}

// ---------------- launch ------------------------------------------------------
extern "C" void kernel_launch(void* const* d_in, const int* in_sizes, int n_in,
                              void* d_out, int out_size) {
    const float* x     = (const float*)d_in[0];
    const float* w_qkv = (const float*)d_in[1];
    const float* b_qkv = (const float*)d_in[2];
    const float* ln_g  = (const float*)d_in[3];
    const float* ln_b  = (const float*)d_in[4];
    const float* w1    = (const float*)d_in[5];
    const float* b1    = (const float*)d_in[6];
    const float* w2    = (const float*)d_in[7];
    const float* b2    = (const float*)d_in[8];
    float* out = (float*)d_out;

    __half *xnh, *qkvh, *hh, *wqkvh, *w1h, *w2h;
    float *x1;
    cudaGetSymbolAddress((void**)&xnh,   g_xnh);
    cudaGetSymbolAddress((void**)&qkvh,  g_qkvh);
    cudaGetSymbolAddress((void**)&x1,    g_x1);
    cudaGetSymbolAddress((void**)&hh,    g_hh);
    cudaGetSymbolAddress((void**)&wqkvh, g_wqkvh);
    cudaGetSymbolAddress((void**)&w1h,   g_w1h);
    cudaGetSymbolAddress((void**)&w2h,   g_w2h);

    cudaFuncSetAttribute(gemm_h<0>, cudaFuncAttributeMaxDynamicSharedMemorySize, GEMM_SMEM_BYTES);
    cudaFuncSetAttribute(gemm_h<1>, cudaFuncAttributeMaxDynamicSharedMemorySize, GEMM_SMEM_BYTES);
    cudaFuncSetAttribute(gemm_h<2>, cudaFuncAttributeMaxDynamicSharedMemorySize, GEMM_SMEM_BYTES);
    cudaFuncSetAttribute(attn_h,    cudaFuncAttributeMaxDynamicSharedMemorySize, ATT_SMEM_BYTES);

    // 0. weights -> fp16
    cvt_kernel<<<(DD * D3) / 1024, 256>>>(w_qkv, wqkvh, DD * D3);
    cvt_kernel<<<(DD * HID) / 1024, 256>>>(w1, w1h, DD * HID);
    cvt_kernel<<<(HID * DD) / 1024, 256>>>(w2, w2h, HID * DD);

    // 1. xnh = LN(x) in fp16
    ln_kernel<<<ROWS, 256>>>(x, ln_g, ln_b, xnh);
    // 2. qkvh = xnh @ wqkv + b_qkv (fp16 out)
    gemm_h<0><<<dim3(D3 / 128, ROWS / 128), 256, GEMM_SMEM_BYTES>>>(
        xnh, wqkvh, b_qkv, nullptr, qkvh, ROWS, D3, DD);
    // 3+4. attention fused with residual: x1 = x + attn
    attn_h<<<dim3(NN / 128, BB * HH), 256, ATT_SMEM_BYTES>>>(qkvh, x, x1);
    // 5. xnh = LN(x1)
    ln_kernel<<<ROWS, 256>>>(x1, ln_g, ln_b, xnh);
    // 6. hh = gelu(xnh @ w1 + b1) (fp16 out)
    gemm_h<1><<<dim3(HID / 128, ROWS / 128), 256, GEMM_SMEM_BYTES>>>(
        xnh, w1h, b1, nullptr, hh, ROWS, HID, DD);
    // 7. out = x1 + hh @ w2 + b2 (fp32 out)
    gemm_h<2><<<dim3(DD / 128, ROWS / 128), 256, GEMM_SMEM_BYTES>>>(
        hh, w2h, b2, x1, out, ROWS, DD, HID);
}